// round 5
// baseline (speedup 1.0000x reference)
#include <cuda_runtime.h>
#include <math.h>
#include <stdint.h>

// ---------------- problem constants ----------------
#define Bn 32
#define Pn 49
#define En 256
#define Hn 256
#define Tn 48
#define STEPS 47
#define Vn 32000
#define INn 792          // E + VP + LB + H + E = 256+8+16+256+256
#define XSn 536          // E + VP + LB + H
#define ROWS (Bn*STEPS)  // 1504

#define ATT_OFF 0
#define LOGP_OFF (ROWS*(Pn+1))                 // 75200
#define TXT_OFF  (LOGP_OFF + (size_t)ROWS*Vn)  // 48203200

// ---------------- scratch (device globals; no allocation) ----------------
__device__ float g_xs  [Bn*XSn];
__device__ float g_h0  [Bn*Hn];
__device__ float g_m0  [Bn*Hn];
__device__ float g_xcat[ROWS*INn];
__device__ float g_xg  [ROWS*4*Hn];
__device__ float4 g_whhR4[Hn*Hn];        // [k*256 + j] = (Wi,Wf,Wg,Wo)[j][k]
__device__ float g_v   [Bn*Pn*Hn];
__device__ float g_hs  [ROWS*Hn];
__device__ float g_fo  [ROWS*2*En];
__device__ float g_hh2 [ROWS*Hn];
__device__ float g_ss2 [ROWS*Hn];
__device__ float g_chh [ROWS*En];
__device__ float g_logits[(size_t)ROWS*Vn]; // ~192 MB

// ---------------- packed f32x2 helpers (Blackwell FFMA2) ----------------
__device__ __forceinline__ unsigned long long fpk(float lo, float hi) {
    unsigned long long r;
    asm("mov.b64 %0, {%1, %2};" : "=l"(r) : "f"(lo), "f"(hi));
    return r;
}
__device__ __forceinline__ void ffma2(unsigned long long& d,
                                      unsigned long long a,
                                      unsigned long long b) {
    asm("fma.rn.f32x2 %0, %1, %2, %3;" : "=l"(d) : "l"(a), "l"(b), "l"(d));
}
__device__ __forceinline__ float2 fup(unsigned long long v) {
    float2 r;
    asm("mov.b64 {%0, %1}, %2;" : "=f"(r.x), "=f"(r.y) : "l"(v));
    return r;
}

__device__ __forceinline__ float sigm(float x) {
    return 1.0f / (1.0f + __expf(-x));
}

// ---------------- prep: image_mean, x_static, h0, m0 ----------------
__global__ void prep_kernel(const float* __restrict__ image,
                            const float* __restrict__ vp,
                            const float* __restrict__ label,
                            const float* __restrict__ topic,
                            const float* __restrict__ Wh, const float* __restrict__ bh,
                            const float* __restrict__ Wm, const float* __restrict__ bm) {
    int b = blockIdx.x;
    int tid = threadIdx.x;   // 256
    __shared__ __align__(16) float im[En];

    float s = 0.f;
    #pragma unroll 7
    for (int p = 0; p < Pn; p++) s += image[(b*Pn + p)*En + tid];
    float mean = s * (1.0f/49.0f);
    im[tid] = mean;

    g_xs[b*XSn + tid] = mean;                       // [0,256) image_mean
    if (tid < 8)  g_xs[b*XSn + 256 + tid] = vp[b*8 + tid];     // [256,264)
    if (tid < 16) g_xs[b*XSn + 264 + tid] = label[b*16 + tid]; // [264,280)
    g_xs[b*XSn + 280 + tid] = topic[b*Hn + tid];               // [280,536)
    __syncthreads();

    float ah = bh[tid], am = bm[tid];
    #pragma unroll 8
    for (int k = 0; k < En; k++) {
        float x = im[k];
        ah = fmaf(x, Wh[tid*En + k], ah);
        am = fmaf(x, Wm[tid*En + k], am);
    }
    g_h0[b*Hn + tid] = tanhf(ah);
    g_m0[b*Hn + tid] = tanhf(am);
}

// ---------------- Whh reorder for coalesced LSTM reads ----------------
__global__ void whh_transpose(const float* __restrict__ Whh) {
    int k = blockIdx.x;   // 256
    int j = threadIdx.x;  // 256
    float4 w;
    w.x = Whh[(0*Hn + j)*Hn + k];
    w.y = Whh[(1*Hn + j)*Hn + k];
    w.z = Whh[(2*Hn + j)*Hn + k];
    w.w = Whh[(3*Hn + j)*Hn + k];
    g_whhR4[k*Hn + j] = w;
}

// ---------------- build concat rows [x_static, emb[text[b,t]]] ----------------
__global__ void xcat_kernel(const int* __restrict__ text,
                            const float* __restrict__ emb) {
    int bt = blockIdx.x;             // 1504
    int b = bt / STEPS, t = bt % STEPS;
    int tid = threadIdx.x;           // 256
    int tok = text[b*Tn + t];
    float* row = g_xcat + (size_t)bt*INn;
    for (int i = tid; i < XSn; i += 256) row[i] = g_xs[b*XSn + i];
    row[XSn + tid] = emb[(size_t)tok*En + tid];
}

// ---------------- generic fp32 GEMM: C[M,N] = A[M,K(lda)] * W[N,K]^T + bias ----------------
// 64x64 tile, 256 threads, 4x4 per thread, FFMA2 inner loop.
__global__ void gemm_tn(const float* __restrict__ A, int lda,
                        const float* __restrict__ W,
                        const float* __restrict__ bias,
                        float* __restrict__ C,
                        int M, int N, int K, int doRelu) {
    __shared__ __align__(16) float As[16][64];
    __shared__ __align__(16) float Bs[16][64];

    const int tid = threadIdx.x;
    const int tx = tid & 15, ty = tid >> 4;
    const int m0 = blockIdx.y * 64, n0 = blockIdx.x * 64;

    unsigned long long acc[4][2];
    #pragma unroll
    for (int i = 0; i < 4; i++) { acc[i][0] = 0ULL; acc[i][1] = 0ULL; }

    for (int k0 = 0; k0 < K; k0 += 16) {
        #pragma unroll
        for (int i = 0; i < 4; i++) {
            int idx = tid + i*256;
            int r = idx >> 4, kk = idx & 15;
            int m = m0 + r, k = k0 + kk, n = n0 + r;
            As[kk][r] = (m < M && k < K) ? A[(size_t)m*lda + k] : 0.f;
            Bs[kk][r] = (n < N && k < K) ? W[(size_t)n*K + k] : 0.f;
        }
        __syncthreads();
        #pragma unroll
        for (int kk = 0; kk < 16; kk++) {
            float4 a4 = *(const float4*)&As[kk][ty*4];
            float4 b4 = *(const float4*)&Bs[kk][tx*4];
            unsigned long long b01 = fpk(b4.x, b4.y);
            unsigned long long b23 = fpk(b4.z, b4.w);
            unsigned long long a0 = fpk(a4.x, a4.x);
            unsigned long long a1 = fpk(a4.y, a4.y);
            unsigned long long a2 = fpk(a4.z, a4.z);
            unsigned long long a3 = fpk(a4.w, a4.w);
            ffma2(acc[0][0], a0, b01); ffma2(acc[0][1], a0, b23);
            ffma2(acc[1][0], a1, b01); ffma2(acc[1][1], a1, b23);
            ffma2(acc[2][0], a2, b01); ffma2(acc[2][1], a2, b23);
            ffma2(acc[3][0], a3, b01); ffma2(acc[3][1], a3, b23);
        }
        __syncthreads();
    }

    #pragma unroll
    for (int i = 0; i < 4; i++) {
        int m = m0 + ty*4 + i;
        if (m >= M) continue;
        float2 v0 = fup(acc[i][0]);
        float2 v1 = fup(acc[i][1]);
        float vals[4] = {v0.x, v0.y, v1.x, v1.y};
        #pragma unroll
        for (int jj = 0; jj < 4; jj++) {
            int n = n0 + tx*4 + jj;
            if (n < N) {
                float o = vals[jj] + bias[n];
                if (doRelu) o = fmaxf(o, 0.f);
                C[(size_t)m*N + n] = o;
            }
        }
    }
}

// ---------------- sequential LSTM (only the carry chain) ----------------
__global__ void lstm_kernel(const float* __restrict__ bhh) {
    int b = blockIdx.x;      // 32
    int j = threadIdx.x;     // 256
    __shared__ __align__(16) float hs[Hn];

    float m = g_m0[b*Hn + j];
    hs[j] = g_h0[b*Hn + j];
    float bi = bhh[j], bf = bhh[256 + j], bg = bhh[512 + j], bo = bhh[768 + j];
    const ulonglong2* W2 = reinterpret_cast<const ulonglong2*>(g_whhR4);
    __syncthreads();

    for (int t = 0; t < STEPS; t++) {
        unsigned long long aIF = 0ULL, aGO = 0ULL;
        #pragma unroll 4
        for (int k0 = 0; k0 < Hn; k0 += 4) {
            float4 h4 = *(const float4*)&hs[k0];
            ulonglong2 w;
            unsigned long long hd;
            w = W2[(k0+0)*Hn + j]; hd = fpk(h4.x, h4.x); ffma2(aIF, hd, w.x); ffma2(aGO, hd, w.y);
            w = W2[(k0+1)*Hn + j]; hd = fpk(h4.y, h4.y); ffma2(aIF, hd, w.x); ffma2(aGO, hd, w.y);
            w = W2[(k0+2)*Hn + j]; hd = fpk(h4.z, h4.z); ffma2(aIF, hd, w.x); ffma2(aGO, hd, w.y);
            w = W2[(k0+3)*Hn + j]; hd = fpk(h4.w, h4.w); ffma2(aIF, hd, w.x); ffma2(aGO, hd, w.y);
        }
        float2 IF = fup(aIF), GO = fup(aGO);
        size_t base = (size_t)(b*STEPS + t) * (4*Hn) + j;
        float gi = g_xg[base]        + bi + IF.x;
        float gf = g_xg[base + 256]  + bf + IF.y;
        float gg = g_xg[base + 512]  + bg + GO.x;
        float go = g_xg[base + 768]  + bo + GO.y;
        m = sigm(gf)*m + sigm(gi)*tanhf(gg);
        float hn = sigm(go)*tanhf(m);
        __syncthreads();
        hs[j] = hn;
        g_hs[(size_t)(b*STEPS + t)*Hn + j] = hn;
        __syncthreads();
    }
}

// ---------------- fused attention per (b,t) ----------------
__global__ void attn_kernel(const float* __restrict__ image,
                            const float* __restrict__ Wz,
                            const float* __restrict__ bz,
                            const int* __restrict__ length,
                            float* __restrict__ dout) {
    int bt = blockIdx.x;               // 1504
    int b = bt / STEPS, t = bt % STEPS;
    int tid = threadIdx.x;             // 128
    int wid = tid >> 5, lane = tid & 31;
    bool valid = t < (length[b] - 1);

    __shared__ float shh2[Hn], shh[Hn], ss[Hn], ss2[Hn];
    __shared__ float zz[Pn+1], aw[Pn+1];

    for (int k = tid; k < Hn; k += 128) {
        shh2[k] = g_hh2[(size_t)bt*Hn + k];
        shh [k] = g_fo [(size_t)bt*2*En + k];
        ss  [k] = g_fo [(size_t)bt*2*En + En + k];
        ss2 [k] = g_ss2[(size_t)bt*Hn + k];
    }
    __syncthreads();

    for (int p = wid; p < Pn+1; p += 4) {
        float part = 0.f;
        const float* vrow = (p < Pn) ? (g_v + (size_t)(b*Pn + p)*Hn) : ss2;
        for (int k = lane; k < Hn; k += 32)
            part += Wz[k] * tanhf(vrow[k] + shh2[k]);
        #pragma unroll
        for (int off = 16; off > 0; off >>= 1)
            part += __shfl_down_sync(0xffffffff, part, off);
        if (lane == 0) zz[p] = part + bz[0];
    }
    __syncthreads();

    if (tid == 0) {
        float mx = zz[0];
        for (int p = 1; p < Pn+1; p++) mx = fmaxf(mx, zz[p]);
        float s = 0.f;
        for (int p = 0; p < Pn+1; p++) { float e = __expf(zz[p]-mx); aw[p] = e; s += e; }
        float inv = 1.f / s;
        for (int p = 0; p < Pn+1; p++) aw[p] *= inv;
    }
    __syncthreads();

    if (tid < Pn+1)
        dout[ATT_OFF + (size_t)bt*(Pn+1) + tid] = valid ? aw[tid] : 0.f;

    for (int k = tid; k < En; k += 128) {
        float c = aw[Pn] * ss[k];
        #pragma unroll 7
        for (int p = 0; p < Pn; p++)
            c = fmaf(aw[p], image[(size_t)(b*Pn + p)*En + k], c);
        g_chh[(size_t)bt*En + k] = c + shh[k];
    }
}

// ---------------- log-softmax + argmax + mask + output ----------------
__global__ void softmax_kernel(const float* __restrict__ temp,
                               const int* __restrict__ length,
                               float* __restrict__ dout) {
    int bt = blockIdx.x;               // 1504
    int b = bt / STEPS, t = bt % STEPS;
    int tid = threadIdx.x;             // 256
    bool valid = t < (length[b] - 1);
    float ls = 1.0f / temp[b];
    const float* row = g_logits + (size_t)bt*Vn;

    __shared__ float smx[256]; __shared__ int sai[256]; __shared__ float ssum[256];

    float mx = -3.402823466e38f; int ai = 0;
    for (int i = tid; i < Vn; i += 256) {
        float l = row[i];
        if (l > mx) { mx = l; ai = i; }
    }
    smx[tid] = mx; sai[tid] = ai; __syncthreads();
    for (int s = 128; s > 0; s >>= 1) {
        if (tid < s) {
            float v2 = smx[tid+s]; int i2 = sai[tid+s];
            if (v2 > smx[tid] || (v2 == smx[tid] && i2 < sai[tid])) { smx[tid] = v2; sai[tid] = i2; }
        }
        __syncthreads();
    }
    mx = smx[0]; ai = sai[0];

    float sum = 0.f;
    for (int i = tid; i < Vn; i += 256)
        sum += __expf((row[i] - mx) * ls);
    ssum[tid] = sum; __syncthreads();
    for (int s = 128; s > 0; s >>= 1) {
        if (tid < s) ssum[tid] += ssum[tid+s];
        __syncthreads();
    }
    float lse = logf(ssum[0]);

    float* lp = dout + LOGP_OFF + (size_t)bt*Vn;
    if (valid) {
        for (int i = tid; i < Vn; i += 256)
            lp[i] = (row[i] - mx)*ls - lse;
    } else {
        for (int i = tid; i < Vn; i += 256)
            lp[i] = 0.f;
    }
    if (tid == 0)
        dout[TXT_OFF + bt] = valid ? (float)ai : 0.f;
}

// ---------------- launcher ----------------
extern "C" void kernel_launch(void* const* d_in, const int* in_sizes, int n_in,
                              void* d_out, int out_size) {
    const float* image = (const float*)d_in[0];
    const float* vp    = (const float*)d_in[1];
    const float* label = (const float*)d_in[2];
    const float* topic = (const float*)d_in[3];
    const float* temp  = (const float*)d_in[4];
    const int*   text  = (const int*)  d_in[5];
    const int*   length= (const int*)  d_in[6];
    const float* emb   = (const float*)d_in[7];
    const float* Wv    = (const float*)d_in[8];
    const float* bv    = (const float*)d_in[9];
    const float* Wh    = (const float*)d_in[10];
    const float* bh    = (const float*)d_in[11];
    const float* Wm    = (const float*)d_in[12];
    const float* bm    = (const float*)d_in[13];
    const float* Wih   = (const float*)d_in[14];
    const float* bih   = (const float*)d_in[15];
    const float* Whh   = (const float*)d_in[16];
    const float* bhh   = (const float*)d_in[17];
    const float* Wfc   = (const float*)d_in[18];
    const float* bfc   = (const float*)d_in[19];
    const float* Whh2  = (const float*)d_in[20];
    const float* bhh2  = (const float*)d_in[21];
    const float* Ws    = (const float*)d_in[22];
    const float* bs    = (const float*)d_in[23];
    const float* Wz    = (const float*)d_in[24];
    const float* bz    = (const float*)d_in[25];
    const float* Wp    = (const float*)d_in[26];
    const float* bp    = (const float*)d_in[27];
    float* dout = (float*)d_out;

    float *p_xcat, *p_xg, *p_v, *p_hs, *p_fo, *p_hh2, *p_ss2, *p_chh, *p_logits;
    cudaGetSymbolAddress((void**)&p_xcat,   g_xcat);
    cudaGetSymbolAddress((void**)&p_xg,     g_xg);
    cudaGetSymbolAddress((void**)&p_v,      g_v);
    cudaGetSymbolAddress((void**)&p_hs,     g_hs);
    cudaGetSymbolAddress((void**)&p_fo,     g_fo);
    cudaGetSymbolAddress((void**)&p_hh2,    g_hh2);
    cudaGetSymbolAddress((void**)&p_ss2,    g_ss2);
    cudaGetSymbolAddress((void**)&p_chh,    g_chh);
    cudaGetSymbolAddress((void**)&p_logits, g_logits);

    prep_kernel<<<Bn, 256>>>(image, vp, label, topic, Wh, bh, Wm, bm);
    whh_transpose<<<Hn, Hn>>>(Whh);
    xcat_kernel<<<ROWS, 256>>>(text, emb);

    // Xg = Xcat @ Wih^T + bih : (1504 x 1024), K=792
    gemm_tn<<<dim3((4*Hn+63)/64, (ROWS+63)/64), 256>>>(p_xcat, INn, Wih, bih, p_xg,
                                                       ROWS, 4*Hn, INn, 0);
    // v = image @ Wv^T + bv : (1568 x 256), K=256
    gemm_tn<<<dim3((Hn+63)/64, (Bn*Pn+63)/64), 256>>>(image, En, Wv, bv, p_v,
                                                      Bn*Pn, Hn, En, 0);
    // sequential LSTM -> g_hs
    lstm_kernel<<<Bn, 256>>>(bhh);

    // fo = relu(Hs @ Wfc^T + bfc) : (1504 x 512)
    gemm_tn<<<dim3((2*En+63)/64, (ROWS+63)/64), 256>>>(p_hs, Hn, Wfc, bfc, p_fo,
                                                       ROWS, 2*En, Hn, 1);
    // _hh = fo[:, :256] @ Whh2^T + bhh2
    gemm_tn<<<dim3((Hn+63)/64, (ROWS+63)/64), 256>>>(p_fo, 2*En, Whh2, bhh2, p_hh2,
                                                     ROWS, Hn, En, 0);
    // _s = fo[:, 256:] @ Ws^T + bs
    gemm_tn<<<dim3((Hn+63)/64, (ROWS+63)/64), 256>>>(p_fo + En, 2*En, Ws, bs, p_ss2,
                                                     ROWS, Hn, En, 0);
    // attention: att out + chh = c + hh
    attn_kernel<<<ROWS, 128>>>(image, Wz, bz, length, dout);

    // logits = chh @ Wp^T + bp : (1504 x 32000), K=256
    gemm_tn<<<dim3((Vn+63)/64, (ROWS+63)/64), 256>>>(p_chh, En, Wp, bp, p_logits,
                                                     ROWS, Vn, En, 0);
    // log-softmax + argmax + masking + outputs
    softmax_kernel<<<ROWS, 256>>>(temp, length, dout);
}

// round 6
// speedup vs baseline: 1.5917x; 1.5917x over previous
#include <cuda_runtime.h>
#include <math.h>
#include <stdint.h>

// ---------------- problem constants ----------------
#define Bn 32
#define Pn 49
#define En 256
#define Hn 256
#define Tn 48
#define STEPS 47
#define Vn 32000
#define INn 792          // E + VP + LB + H + E = 256+8+16+256+256
#define XSn 536          // E + VP + LB + H
#define ROWS (Bn*STEPS)  // 1504

#define ATT_OFF 0
#define LOGP_OFF (ROWS*(Pn+1))                 // 75200
#define TXT_OFF  (LOGP_OFF + (size_t)ROWS*Vn)  // 48203200

// ---------------- scratch (device globals; no allocation) ----------------
__device__ float g_xs  [Bn*XSn];
__device__ float g_h0  [Bn*Hn];
__device__ float g_m0  [Bn*Hn];
__device__ float g_xcat[ROWS*INn];
__device__ float g_xg  [ROWS*4*Hn];
__device__ float4 g_whhR4[Hn*Hn];        // [k*256 + j] = (Wi,Wf,Wg,Wo)[j][k]
__device__ float g_v   [Bn*Pn*Hn];
__device__ float g_hs  [ROWS*Hn];
__device__ float g_fo  [ROWS*2*En];
__device__ float g_hh2 [ROWS*Hn];
__device__ float g_ss2 [ROWS*Hn];
__device__ float g_chh [ROWS*En];
__device__ float g_logits[(size_t)ROWS*Vn]; // ~192 MB

// ---------------- packed f32x2 helpers (Blackwell FFMA2) ----------------
__device__ __forceinline__ unsigned long long fpk(float lo, float hi) {
    unsigned long long r;
    asm("mov.b64 %0, {%1, %2};" : "=l"(r) : "f"(lo), "f"(hi));
    return r;
}
__device__ __forceinline__ void ffma2(unsigned long long& d,
                                      unsigned long long a,
                                      unsigned long long b) {
    asm("fma.rn.f32x2 %0, %1, %2, %3;" : "=l"(d) : "l"(a), "l"(b), "l"(d));
}
__device__ __forceinline__ float2 fup(unsigned long long v) {
    float2 r;
    asm("mov.b64 {%0, %1}, %2;" : "=f"(r.x), "=f"(r.y) : "l"(v));
    return r;
}

__device__ __forceinline__ float sigm(float x) {
    return 1.0f / (1.0f + __expf(-x));
}

// ---------------- prep: image_mean, x_static, h0, m0 ----------------
__global__ void prep_kernel(const float* __restrict__ image,
                            const float* __restrict__ vp,
                            const float* __restrict__ label,
                            const float* __restrict__ topic,
                            const float* __restrict__ Wh, const float* __restrict__ bh,
                            const float* __restrict__ Wm, const float* __restrict__ bm) {
    int b = blockIdx.x;
    int tid = threadIdx.x;   // 256
    __shared__ __align__(16) float im[En];

    float s = 0.f;
    #pragma unroll 7
    for (int p = 0; p < Pn; p++) s += image[(b*Pn + p)*En + tid];
    float mean = s * (1.0f/49.0f);
    im[tid] = mean;

    g_xs[b*XSn + tid] = mean;
    if (tid < 8)  g_xs[b*XSn + 256 + tid] = vp[b*8 + tid];
    if (tid < 16) g_xs[b*XSn + 264 + tid] = label[b*16 + tid];
    g_xs[b*XSn + 280 + tid] = topic[b*Hn + tid];
    __syncthreads();

    float ah = bh[tid], am = bm[tid];
    #pragma unroll 8
    for (int k = 0; k < En; k++) {
        float x = im[k];
        ah = fmaf(x, Wh[tid*En + k], ah);
        am = fmaf(x, Wm[tid*En + k], am);
    }
    g_h0[b*Hn + tid] = tanhf(ah);
    g_m0[b*Hn + tid] = tanhf(am);
}

// ---------------- Whh reorder for coalesced LSTM reads ----------------
__global__ void whh_transpose(const float* __restrict__ Whh) {
    int k = blockIdx.x;
    int j = threadIdx.x;
    float4 w;
    w.x = Whh[(0*Hn + j)*Hn + k];
    w.y = Whh[(1*Hn + j)*Hn + k];
    w.z = Whh[(2*Hn + j)*Hn + k];
    w.w = Whh[(3*Hn + j)*Hn + k];
    g_whhR4[k*Hn + j] = w;
}

// ---------------- build concat rows [x_static, emb[text[b,t]]] ----------------
__global__ void xcat_kernel(const int* __restrict__ text,
                            const float* __restrict__ emb) {
    int bt = blockIdx.x;
    int b = bt / STEPS, t = bt % STEPS;
    int tid = threadIdx.x;
    int tok = text[b*Tn + t];
    float* row = g_xcat + (size_t)bt*INn;
    for (int i = tid; i < XSn; i += 256) row[i] = g_xs[b*XSn + i];
    row[XSn + tid] = emb[(size_t)tok*En + tid];
}

// ============== big-tile fp32 GEMM: C[M,N] = A[M,K(lda)] @ W[N,K]^T + bias ==============
// 128x128 tile, 256 threads, 8x8 per thread, FFMA2, double-buffered smem.
#define SPAD 132
__global__ __launch_bounds__(256, 2)
void gemm_tn128(const float* __restrict__ A, int lda,
                const float* __restrict__ W,
                const float* __restrict__ bias,
                float* __restrict__ C,
                int M, int N, int K, int doRelu) {
    __shared__ __align__(16) float As[2][16][SPAD];
    __shared__ __align__(16) float Bs[2][16][SPAD];

    const int tid = threadIdx.x;
    const int tx = tid & 15, ty = tid >> 4;
    const int m0 = blockIdx.y * 128, n0 = blockIdx.x * 128;

    const int lr = tid >> 2;          // 0..63
    const int lk = (tid & 3) * 4;     // 0,4,8,12

    unsigned long long acc[8][4];
    #pragma unroll
    for (int i = 0; i < 8; i++)
        #pragma unroll
        for (int j = 0; j < 4; j++) acc[i][j] = 0ULL;

    const int KT = (K + 15) / 16;
    const float4 z4 = make_float4(0.f, 0.f, 0.f, 0.f);
    float4 fa0, fa1, fb0, fb1;

    // prologue: load tile 0
    {
        int k = lk;
        bool kok = (k < K);
        int mA0 = m0 + lr, mA1 = m0 + lr + 64;
        int nB0 = n0 + lr, nB1 = n0 + lr + 64;
        fa0 = (kok && mA0 < M) ? *(const float4*)&A[(size_t)mA0*lda + k] : z4;
        fa1 = (kok && mA1 < M) ? *(const float4*)&A[(size_t)mA1*lda + k] : z4;
        fb0 = (kok && nB0 < N) ? *(const float4*)&W[(size_t)nB0*K + k] : z4;
        fb1 = (kok && nB1 < N) ? *(const float4*)&W[(size_t)nB1*K + k] : z4;
    }
    As[0][lk+0][lr] = fa0.x; As[0][lk+1][lr] = fa0.y; As[0][lk+2][lr] = fa0.z; As[0][lk+3][lr] = fa0.w;
    As[0][lk+0][lr+64] = fa1.x; As[0][lk+1][lr+64] = fa1.y; As[0][lk+2][lr+64] = fa1.z; As[0][lk+3][lr+64] = fa1.w;
    Bs[0][lk+0][lr] = fb0.x; Bs[0][lk+1][lr] = fb0.y; Bs[0][lk+2][lr] = fb0.z; Bs[0][lk+3][lr] = fb0.w;
    Bs[0][lk+0][lr+64] = fb1.x; Bs[0][lk+1][lr+64] = fb1.y; Bs[0][lk+2][lr+64] = fb1.z; Bs[0][lk+3][lr+64] = fb1.w;
    __syncthreads();

    for (int kt = 0; kt < KT; kt++) {
        int cur = kt & 1;
        if (kt + 1 < KT) {
            int k = (kt + 1) * 16 + lk;
            bool kok = (k < K);
            int mA0 = m0 + lr, mA1 = m0 + lr + 64;
            int nB0 = n0 + lr, nB1 = n0 + lr + 64;
            fa0 = (kok && mA0 < M) ? *(const float4*)&A[(size_t)mA0*lda + k] : z4;
            fa1 = (kok && mA1 < M) ? *(const float4*)&A[(size_t)mA1*lda + k] : z4;
            fb0 = (kok && nB0 < N) ? *(const float4*)&W[(size_t)nB0*K + k] : z4;
            fb1 = (kok && nB1 < N) ? *(const float4*)&W[(size_t)nB1*K + k] : z4;
        }
        #pragma unroll
        for (int kk = 0; kk < 16; kk++) {
            float4 a0 = *(const float4*)&As[cur][kk][ty*8];
            float4 a1 = *(const float4*)&As[cur][kk][ty*8 + 4];
            float4 b0 = *(const float4*)&Bs[cur][kk][tx*8];
            float4 b1 = *(const float4*)&Bs[cur][kk][tx*8 + 4];
            unsigned long long bp0 = fpk(b0.x, b0.y);
            unsigned long long bp1 = fpk(b0.z, b0.w);
            unsigned long long bp2 = fpk(b1.x, b1.y);
            unsigned long long bp3 = fpk(b1.z, b1.w);
            float av[8] = {a0.x, a0.y, a0.z, a0.w, a1.x, a1.y, a1.z, a1.w};
            #pragma unroll
            for (int i = 0; i < 8; i++) {
                unsigned long long ad = fpk(av[i], av[i]);
                ffma2(acc[i][0], ad, bp0);
                ffma2(acc[i][1], ad, bp1);
                ffma2(acc[i][2], ad, bp2);
                ffma2(acc[i][3], ad, bp3);
            }
        }
        if (kt + 1 < KT) {
            int nxt = cur ^ 1;
            As[nxt][lk+0][lr] = fa0.x; As[nxt][lk+1][lr] = fa0.y; As[nxt][lk+2][lr] = fa0.z; As[nxt][lk+3][lr] = fa0.w;
            As[nxt][lk+0][lr+64] = fa1.x; As[nxt][lk+1][lr+64] = fa1.y; As[nxt][lk+2][lr+64] = fa1.z; As[nxt][lk+3][lr+64] = fa1.w;
            Bs[nxt][lk+0][lr] = fb0.x; Bs[nxt][lk+1][lr] = fb0.y; Bs[nxt][lk+2][lr] = fb0.z; Bs[nxt][lk+3][lr] = fb0.w;
            Bs[nxt][lk+0][lr+64] = fb1.x; Bs[nxt][lk+1][lr+64] = fb1.y; Bs[nxt][lk+2][lr+64] = fb1.z; Bs[nxt][lk+3][lr+64] = fb1.w;
            __syncthreads();
        }
    }

    // epilogue
    int nb = n0 + tx*8;
    float bvals[8];
    #pragma unroll
    for (int j = 0; j < 8; j++) bvals[j] = (nb + j < N) ? bias[nb + j] : 0.f;

    #pragma unroll
    for (int i = 0; i < 8; i++) {
        int m = m0 + ty*8 + i;
        if (m >= M) continue;
        float out[8];
        #pragma unroll
        for (int j = 0; j < 4; j++) {
            float2 v = fup(acc[i][j]);
            out[2*j]   = v.x + bvals[2*j];
            out[2*j+1] = v.y + bvals[2*j+1];
        }
        if (doRelu) {
            #pragma unroll
            for (int j = 0; j < 8; j++) out[j] = fmaxf(out[j], 0.f);
        }
        if (nb + 7 < N) {
            *(float4*)&C[(size_t)m*N + nb]     = make_float4(out[0], out[1], out[2], out[3]);
            *(float4*)&C[(size_t)m*N + nb + 4] = make_float4(out[4], out[5], out[6], out[7]);
        } else {
            #pragma unroll
            for (int j = 0; j < 8; j++)
                if (nb + j < N) C[(size_t)m*N + nb + j] = out[j];
        }
    }
}

// ---------------- small fp32 GEMM (64x64 tile) for the N=256 matmuls ----------------
__global__ void gemm_tn(const float* __restrict__ A, int lda,
                        const float* __restrict__ W,
                        const float* __restrict__ bias,
                        float* __restrict__ C,
                        int M, int N, int K, int doRelu) {
    __shared__ __align__(16) float As[16][64];
    __shared__ __align__(16) float Bs[16][64];

    const int tid = threadIdx.x;
    const int tx = tid & 15, ty = tid >> 4;
    const int m0 = blockIdx.y * 64, n0 = blockIdx.x * 64;

    unsigned long long acc[4][2];
    #pragma unroll
    for (int i = 0; i < 4; i++) { acc[i][0] = 0ULL; acc[i][1] = 0ULL; }

    for (int k0 = 0; k0 < K; k0 += 16) {
        #pragma unroll
        for (int i = 0; i < 4; i++) {
            int idx = tid + i*256;
            int r = idx >> 4, kk = idx & 15;
            int m = m0 + r, k = k0 + kk, n = n0 + r;
            As[kk][r] = (m < M && k < K) ? A[(size_t)m*lda + k] : 0.f;
            Bs[kk][r] = (n < N && k < K) ? W[(size_t)n*K + k] : 0.f;
        }
        __syncthreads();
        #pragma unroll
        for (int kk = 0; kk < 16; kk++) {
            float4 a4 = *(const float4*)&As[kk][ty*4];
            float4 b4 = *(const float4*)&Bs[kk][tx*4];
            unsigned long long b01 = fpk(b4.x, b4.y);
            unsigned long long b23 = fpk(b4.z, b4.w);
            unsigned long long a0 = fpk(a4.x, a4.x);
            unsigned long long a1 = fpk(a4.y, a4.y);
            unsigned long long a2 = fpk(a4.z, a4.z);
            unsigned long long a3 = fpk(a4.w, a4.w);
            ffma2(acc[0][0], a0, b01); ffma2(acc[0][1], a0, b23);
            ffma2(acc[1][0], a1, b01); ffma2(acc[1][1], a1, b23);
            ffma2(acc[2][0], a2, b01); ffma2(acc[2][1], a2, b23);
            ffma2(acc[3][0], a3, b01); ffma2(acc[3][1], a3, b23);
        }
        __syncthreads();
    }

    #pragma unroll
    for (int i = 0; i < 4; i++) {
        int m = m0 + ty*4 + i;
        if (m >= M) continue;
        float2 v0 = fup(acc[i][0]);
        float2 v1 = fup(acc[i][1]);
        float vals[4] = {v0.x, v0.y, v1.x, v1.y};
        #pragma unroll
        for (int jj = 0; jj < 4; jj++) {
            int n = n0 + tx*4 + jj;
            if (n < N) {
                float o = vals[jj] + bias[n];
                if (doRelu) o = fmaxf(o, 0.f);
                C[(size_t)m*N + n] = o;
            }
        }
    }
}

// ---------------- sequential LSTM (only the carry chain) ----------------
__global__ void lstm_kernel(const float* __restrict__ bhh) {
    int b = blockIdx.x;      // 32
    int j = threadIdx.x;     // 256
    __shared__ __align__(16) float hs[Hn];

    float m = g_m0[b*Hn + j];
    hs[j] = g_h0[b*Hn + j];
    float bi = bhh[j], bf = bhh[256 + j], bg = bhh[512 + j], bo = bhh[768 + j];
    const ulonglong2* W2 = reinterpret_cast<const ulonglong2*>(g_whhR4);
    __syncthreads();

    for (int t = 0; t < STEPS; t++) {
        unsigned long long aIF = 0ULL, aGO = 0ULL;
        #pragma unroll 4
        for (int k0 = 0; k0 < Hn; k0 += 4) {
            float4 h4 = *(const float4*)&hs[k0];
            ulonglong2 w;
            unsigned long long hd;
            w = W2[(k0+0)*Hn + j]; hd = fpk(h4.x, h4.x); ffma2(aIF, hd, w.x); ffma2(aGO, hd, w.y);
            w = W2[(k0+1)*Hn + j]; hd = fpk(h4.y, h4.y); ffma2(aIF, hd, w.x); ffma2(aGO, hd, w.y);
            w = W2[(k0+2)*Hn + j]; hd = fpk(h4.z, h4.z); ffma2(aIF, hd, w.x); ffma2(aGO, hd, w.y);
            w = W2[(k0+3)*Hn + j]; hd = fpk(h4.w, h4.w); ffma2(aIF, hd, w.x); ffma2(aGO, hd, w.y);
        }
        float2 IF = fup(aIF), GO = fup(aGO);
        size_t base = (size_t)(b*STEPS + t) * (4*Hn) + j;
        float gi = g_xg[base]        + bi + IF.x;
        float gf = g_xg[base + 256]  + bf + IF.y;
        float gg = g_xg[base + 512]  + bg + GO.x;
        float go = g_xg[base + 768]  + bo + GO.y;
        m = sigm(gf)*m + sigm(gi)*tanhf(gg);
        float hn = sigm(go)*tanhf(m);
        __syncthreads();
        hs[j] = hn;
        g_hs[(size_t)(b*STEPS + t)*Hn + j] = hn;
        __syncthreads();
    }
}

// ---------------- fused attention per (b,t) ----------------
__global__ void attn_kernel(const float* __restrict__ image,
                            const float* __restrict__ Wz,
                            const float* __restrict__ bz,
                            const int* __restrict__ length,
                            float* __restrict__ dout) {
    int bt = blockIdx.x;
    int b = bt / STEPS, t = bt % STEPS;
    int tid = threadIdx.x;             // 128
    int wid = tid >> 5, lane = tid & 31;
    bool valid = t < (length[b] - 1);

    __shared__ float shh2[Hn], shh[Hn], ss[Hn], ss2[Hn];
    __shared__ float zz[Pn+1], aw[Pn+1];

    for (int k = tid; k < Hn; k += 128) {
        shh2[k] = g_hh2[(size_t)bt*Hn + k];
        shh [k] = g_fo [(size_t)bt*2*En + k];
        ss  [k] = g_fo [(size_t)bt*2*En + En + k];
        ss2 [k] = g_ss2[(size_t)bt*Hn + k];
    }
    __syncthreads();

    for (int p = wid; p < Pn+1; p += 4) {
        float part = 0.f;
        const float* vrow = (p < Pn) ? (g_v + (size_t)(b*Pn + p)*Hn) : ss2;
        for (int k = lane; k < Hn; k += 32)
            part += Wz[k] * tanhf(vrow[k] + shh2[k]);
        #pragma unroll
        for (int off = 16; off > 0; off >>= 1)
            part += __shfl_down_sync(0xffffffff, part, off);
        if (lane == 0) zz[p] = part + bz[0];
    }
    __syncthreads();

    if (tid == 0) {
        float mx = zz[0];
        for (int p = 1; p < Pn+1; p++) mx = fmaxf(mx, zz[p]);
        float s = 0.f;
        for (int p = 0; p < Pn+1; p++) { float e = __expf(zz[p]-mx); aw[p] = e; s += e; }
        float inv = 1.f / s;
        for (int p = 0; p < Pn+1; p++) aw[p] *= inv;
    }
    __syncthreads();

    if (tid < Pn+1)
        dout[ATT_OFF + (size_t)bt*(Pn+1) + tid] = valid ? aw[tid] : 0.f;

    for (int k = tid; k < En; k += 128) {
        float c = aw[Pn] * ss[k];
        #pragma unroll 7
        for (int p = 0; p < Pn; p++)
            c = fmaf(aw[p], image[(size_t)(b*Pn + p)*En + k], c);
        g_chh[(size_t)bt*En + k] = c + shh[k];
    }
}

// ---------------- log-softmax + argmax + mask + output (vectorized, 512 thr) ----------------
__global__ void softmax_kernel(const float* __restrict__ temp,
                               const int* __restrict__ length,
                               float* __restrict__ dout) {
    int bt = blockIdx.x;
    int b = bt / STEPS, t = bt % STEPS;
    int tid = threadIdx.x;             // 512
    bool valid = t < (length[b] - 1);
    float ls = 1.0f / temp[b];
    const float4* row4 = (const float4*)(g_logits + (size_t)bt*Vn);  // 8000 float4
    float4* lp4 = (float4*)(dout + LOGP_OFF + (size_t)bt*Vn);

    __shared__ float smx[512]; __shared__ int sai[512]; __shared__ float ssum[512];

    if (!valid) {
        float4 z = make_float4(0.f, 0.f, 0.f, 0.f);
        for (int i = tid; i < Vn/4; i += 512) lp4[i] = z;
        if (tid == 0) dout[TXT_OFF + bt] = 0.f;
        return;
    }

    float mx = -3.402823466e38f; int ai = 0;
    for (int i = tid; i < Vn/4; i += 512) {
        float4 v = row4[i];
        if (v.x > mx) { mx = v.x; ai = 4*i; }
        if (v.y > mx) { mx = v.y; ai = 4*i+1; }
        if (v.z > mx) { mx = v.z; ai = 4*i+2; }
        if (v.w > mx) { mx = v.w; ai = 4*i+3; }
    }
    smx[tid] = mx; sai[tid] = ai; __syncthreads();
    for (int s = 256; s > 0; s >>= 1) {
        if (tid < s) {
            float v2 = smx[tid+s]; int i2 = sai[tid+s];
            if (v2 > smx[tid] || (v2 == smx[tid] && i2 < sai[tid])) { smx[tid] = v2; sai[tid] = i2; }
        }
        __syncthreads();
    }
    mx = smx[0]; ai = sai[0];

    float sum = 0.f;
    for (int i = tid; i < Vn/4; i += 512) {
        float4 v = row4[i];
        sum += __expf((v.x - mx)*ls) + __expf((v.y - mx)*ls)
             + __expf((v.z - mx)*ls) + __expf((v.w - mx)*ls);
    }
    ssum[tid] = sum; __syncthreads();
    for (int s = 256; s > 0; s >>= 1) {
        if (tid < s) ssum[tid] += ssum[tid+s];
        __syncthreads();
    }
    float lse = logf(ssum[0]);

    for (int i = tid; i < Vn/4; i += 512) {
        float4 v = row4[i];
        float4 o;
        o.x = (v.x - mx)*ls - lse;
        o.y = (v.y - mx)*ls - lse;
        o.z = (v.z - mx)*ls - lse;
        o.w = (v.w - mx)*ls - lse;
        lp4[i] = o;
    }
    if (tid == 0) dout[TXT_OFF + bt] = (float)ai;
}

// ---------------- launcher ----------------
extern "C" void kernel_launch(void* const* d_in, const int* in_sizes, int n_in,
                              void* d_out, int out_size) {
    const float* image = (const float*)d_in[0];
    const float* vp    = (const float*)d_in[1];
    const float* label = (const float*)d_in[2];
    const float* topic = (const float*)d_in[3];
    const float* temp  = (const float*)d_in[4];
    const int*   text  = (const int*)  d_in[5];
    const int*   length= (const int*)  d_in[6];
    const float* emb   = (const float*)d_in[7];
    const float* Wv    = (const float*)d_in[8];
    const float* bv    = (const float*)d_in[9];
    const float* Wh    = (const float*)d_in[10];
    const float* bh    = (const float*)d_in[11];
    const float* Wm    = (const float*)d_in[12];
    const float* bm    = (const float*)d_in[13];
    const float* Wih   = (const float*)d_in[14];
    const float* bih   = (const float*)d_in[15];
    const float* Whh   = (const float*)d_in[16];
    const float* bhh   = (const float*)d_in[17];
    const float* Wfc   = (const float*)d_in[18];
    const float* bfc   = (const float*)d_in[19];
    const float* Whh2  = (const float*)d_in[20];
    const float* bhh2  = (const float*)d_in[21];
    const float* Ws    = (const float*)d_in[22];
    const float* bs    = (const float*)d_in[23];
    const float* Wz    = (const float*)d_in[24];
    const float* bz    = (const float*)d_in[25];
    const float* Wp    = (const float*)d_in[26];
    const float* bp    = (const float*)d_in[27];
    float* dout = (float*)d_out;

    float *p_xcat, *p_xg, *p_v, *p_hs, *p_fo, *p_hh2, *p_ss2, *p_chh, *p_logits;
    cudaGetSymbolAddress((void**)&p_xcat,   g_xcat);
    cudaGetSymbolAddress((void**)&p_xg,     g_xg);
    cudaGetSymbolAddress((void**)&p_v,      g_v);
    cudaGetSymbolAddress((void**)&p_hs,     g_hs);
    cudaGetSymbolAddress((void**)&p_fo,     g_fo);
    cudaGetSymbolAddress((void**)&p_hh2,    g_hh2);
    cudaGetSymbolAddress((void**)&p_ss2,    g_ss2);
    cudaGetSymbolAddress((void**)&p_chh,    g_chh);
    cudaGetSymbolAddress((void**)&p_logits, g_logits);

    prep_kernel<<<Bn, 256>>>(image, vp, label, topic, Wh, bh, Wm, bm);
    whh_transpose<<<Hn, Hn>>>(Whh);
    xcat_kernel<<<ROWS, 256>>>(text, emb);

    // Xg = Xcat @ Wih^T + bih : (1504 x 1024), K=792  -> big-tile GEMM
    gemm_tn128<<<dim3((4*Hn+127)/128, (ROWS+127)/128), 256>>>(p_xcat, INn, Wih, bih, p_xg,
                                                              ROWS, 4*Hn, INn, 0);
    // v = image @ Wv^T + bv : (1568 x 256), K=256
    gemm_tn<<<dim3((Hn+63)/64, (Bn*Pn+63)/64), 256>>>(image, En, Wv, bv, p_v,
                                                      Bn*Pn, Hn, En, 0);
    // sequential LSTM -> g_hs
    lstm_kernel<<<Bn, 256>>>(bhh);

    // fo = relu(Hs @ Wfc^T + bfc) : (1504 x 512)
    gemm_tn<<<dim3((2*En+63)/64, (ROWS+63)/64), 256>>>(p_hs, Hn, Wfc, bfc, p_fo,
                                                       ROWS, 2*En, Hn, 1);
    // _hh = fo[:, :256] @ Whh2^T + bhh2
    gemm_tn<<<dim3((Hn+63)/64, (ROWS+63)/64), 256>>>(p_fo, 2*En, Whh2, bhh2, p_hh2,
                                                     ROWS, Hn, En, 0);
    // _s = fo[:, 256:] @ Ws^T + bs
    gemm_tn<<<dim3((Hn+63)/64, (ROWS+63)/64), 256>>>(p_fo + En, 2*En, Ws, bs, p_ss2,
                                                     ROWS, Hn, En, 0);
    // attention: att out + chh = c + hh
    attn_kernel<<<ROWS, 128>>>(image, Wz, bz, length, dout);

    // logits = chh @ Wp^T + bp : (1504 x 32000), K=256 -> big-tile GEMM
    gemm_tn128<<<dim3((Vn+127)/128, (ROWS+127)/128), 256>>>(p_chh, En, Wp, bp, p_logits,
                                                            ROWS, Vn, En, 0);
    // log-softmax + argmax + masking + outputs
    softmax_kernel<<<ROWS, 512>>>(temp, length, dout);
}